// round 11
// baseline (speedup 1.0000x reference)
#include <cuda_runtime.h>
#include <cuda_fp16.h>
#include <cstdint>

// Shapes (fixed)
#define NB 4
#define NG 4096
#define DZ 128
#define NT 2048

// Tiling
#define MT 32              // t rows per CTA
#define GC 64              // g per chunk
#define NCHUNK (NG/GC)     // 64
#define ZROW 132           // u32 stride per g-pair row
#define TILE_U32 4608      // 32*ZROW(4224) + gmeta 256 + bbox/pad 128
#define TILE_BYTES (TILE_U32*4)     // 18432 = 128thr*9*16B
#define NTHREADS 128       // 4 warps: 2 mh x 2 gs (both kk per warp)
#define PTHREADS 256
#define SKIP_THR (-26.0f)  // exp2 arg threshold: w < 2^-26 -> negligible

typedef unsigned int u32;

__device__ __align__(16) u32 g_Zh[(size_t)NB * NCHUNK * TILE_U32];
__device__ u32 g_perm_t[NB][NT];
__device__ u32 g_perm_g[NB][NG];

__device__ __forceinline__ float ex2f(float x) {
    float y; asm("ex2.approx.f32 %0, %1;" : "=f"(y) : "f"(x)); return y;
}
__device__ __forceinline__ u32 f16x2(float lo, float hi) {
    u32 d; asm("cvt.rn.f16x2.f32 %0, %1, %2;" : "=r"(d) : "f"(hi), "f"(lo)); return d;
}
__device__ __forceinline__ u32 smem_u32(const void* p) {
    u32 a;
    asm("{ .reg .u64 t; cvta.to.shared.u64 t, %1; cvt.u32.u64 %0, t; }" : "=r"(a) : "l"(p));
    return a;
}
__device__ __forceinline__ void mma16816(float* c, u32 a0, u32 a1, u32 a2, u32 a3,
                                         u32 b0, u32 b1) {
    asm("mma.sync.aligned.m16n8k16.row.col.f32.f16.f16.f32 "
        "{%0,%1,%2,%3}, {%4,%5,%6,%7}, {%8,%9}, {%0,%1,%2,%3};"
        : "+f"(c[0]), "+f"(c[1]), "+f"(c[2]), "+f"(c[3])
        : "r"(a0), "r"(a1), "r"(a2), "r"(a3), "r"(b0), "r"(b1));
}
__device__ __forceinline__ u32 part1by1(u32 x) {
    x &= 0xFFFF;
    x = (x | (x << 8)) & 0x00FF00FF;
    x = (x | (x << 4)) & 0x0F0F0F0F;
    x = (x | (x << 2)) & 0x33333333;
    x = (x | (x << 1)) & 0x55555555;
    return x;
}
__device__ __forceinline__ void softplus_cc(const float* lsp, int kk, float& c0, float& c1) {
    const float HL2E = 0.7213475204444817f;
    float p0 = lsp[0 * 2 + kk], p1 = lsp[1 * 2 + kk];
    float sp0 = (p0 > 20.f) ? p0 : log1pf(expf(p0));
    float sp1 = (p1 > 20.f) ? p1 : log1pf(expf(p1));
    float i0 = 1.f / (1e-5f + sp0), i1 = 1.f / (1e-5f + sp1);
    c0 = -HL2E * i0 * i0;
    c1 = -HL2E * i1 * i1;
}

// ---------------- kernel 0: deterministic Morton sort (bitonic) --------------
__global__ void __launch_bounds__(512)
sort_pts(const float* __restrict__ xt_all, const float* __restrict__ xg_all)
{
    __shared__ u32 keys[4096];
    const int b   = blockIdx.x >> 1;
    const int isG = blockIdx.x & 1;
    const int n   = isG ? NG : NT;
    const float2* src = (const float2*)(isG ? xg_all + (size_t)b * NG * 2
                                            : xt_all + (size_t)b * NT * 2);
    const int tid = threadIdx.x;

    for (int i = tid; i < n; i += 512) {
        float2 v = src[i];
        int mx = min(31, max(0, (int)(v.x * 32.f)));
        int my = min(31, max(0, (int)(v.y * 32.f)));
        u32 mc = (part1by1((u32)mx) | (part1by1((u32)my) << 1)) & 0x3FF;
        keys[i] = (mc << 12) | (u32)i;
    }
    __syncthreads();
    for (int k = 2; k <= n; k <<= 1) {
        for (int j = k >> 1; j > 0; j >>= 1) {
            for (int i = tid; i < n; i += 512) {
                int l = i ^ j;
                if (l > i) {
                    u32 a = keys[i], c = keys[l];
                    bool up = ((i & k) == 0);
                    if ((a > c) == up) { keys[i] = c; keys[l] = a; }
                }
            }
            __syncthreads();
        }
    }
    u32* dst = isG ? g_perm_g[b] : g_perm_t[b];
    for (int i = tid; i < n; i += 512) dst[i] = keys[i] & 0xFFF;
}

// ---------------- kernel 1: pack sorted tiles + gmeta + chunk bbox -----------
__global__ void __launch_bounds__(PTHREADS)
prep_tiles(const float* __restrict__ zg_all, const float* __restrict__ xg_all,
           const float* __restrict__ lsp)
{
    __shared__ float sx[GC], sy[GC];
    const int bc  = blockIdx.x;
    const int b   = bc >> 6;
    const int gc  = bc & 63;
    const int tid = threadIdx.x;
    const int w   = tid >> 5;
    const int z4  = tid & 31;

    u32* tile = g_Zh + (size_t)bc * TILE_U32;
    const u32* pg = g_perm_g[b] + gc * GC;

#pragma unroll
    for (int it = 0; it < 4; ++it) {
        int gp = w + it * 8;
        u32 r0 = pg[2 * gp], r1 = pg[2 * gp + 1];
        float4 v0 = __ldg((const float4*)(zg_all + ((size_t)b * NG + r0) * DZ) + z4);
        float4 v1 = __ldg((const float4*)(zg_all + ((size_t)b * NG + r1) * DZ) + z4);
        u32* dst = tile + gp * ZROW;
        int p0 = (z4 & 1) * 64 + (z4 >> 1);
        dst[p0]      = f16x2(v0.x, v1.x);
        dst[p0 + 16] = f16x2(v0.y, v1.y);
        dst[p0 + 32] = f16x2(v0.z, v1.z);
        dst[p0 + 48] = f16x2(v0.w, v1.w);
    }

    if (tid < GC) {
        float c00, c01, c10, c11;
        softplus_cc(lsp, 0, c00, c01);
        softplus_cc(lsp, 1, c10, c11);
        u32 pgi = pg[tid];
        float2 xgv = __ldg((const float2*)xg_all + (size_t)b * NG + pgi);
        float s0 = xgv.x * xgv.x, s1 = xgv.y * xgv.y;
        float Bg0 = fmaf(s0, c00, s1 * c01);
        float Bg1 = fmaf(s0, c10, s1 * c11);
        ((float4*)(tile + 32 * ZROW))[tid] = make_float4(xgv.x, xgv.y, Bg0, Bg1);
        sx[tid] = xgv.x; sy[tid] = xgv.y;
    }
    __syncthreads();
    if (tid == 0) {
        float mnx = 1e30f, mxx = -1e30f, mny = 1e30f, mxy = -1e30f;
        for (int i = 0; i < GC; ++i) {
            mnx = fminf(mnx, sx[i]); mxx = fmaxf(mxx, sx[i]);
            mny = fminf(mny, sy[i]); mxy = fmaxf(mxy, sy[i]);
        }
        ((float4*)(tile + 32 * ZROW + 256))[0] = make_float4(mnx, mxx, mny, mxy);
    }
}

// -------- A-fragment builder: one slice, one kk --------
__device__ __forceinline__ void build_a(
    const float4* m, int kk,
    const float (&At)[2][2], const float (&u0)[2][2], const float (&u1)[2][2],
    u32 (&a)[4])
{
    float wvA[4], wvB[4];
#pragma unroll
    for (int i = 0; i < 4; ++i) {
        float Bv = kk ? m[i].w : m[i].z;
        wvA[i] = ex2f(fmaf(m[i].x, u0[0][kk], fmaf(m[i].y, u1[0][kk], Bv)) + At[0][kk]);
        wvB[i] = ex2f(fmaf(m[i].x, u0[1][kk], fmaf(m[i].y, u1[1][kk], Bv)) + At[1][kk]);
    }
    a[0] = f16x2(wvA[0], wvA[1]);
    a[1] = f16x2(wvB[0], wvB[1]);
    a[2] = f16x2(wvA[2], wvA[3]);
    a[3] = f16x2(wvB[2], wvB[3]);
}

// -------- per-chunk compute with per-kk skip --------
__device__ __forceinline__ void do_chunk(
    const u32* bu0, const u32* bu1, const float4* gm0, const float4* gm1,
    bool sk0, bool sk1,
    const float (&At)[2][2], const float (&u0)[2][2], const float (&u1)[2][2],
    float (&c)[2][16][4])
{
    if (sk0 && sk1) return;
    float4 n0[4] = { gm0[0], gm0[1], gm0[8], gm0[9] };
    float4 n1[4] = { gm1[0], gm1[1], gm1[8], gm1[9] };
    u32 a[2][2][4];   // [slice][kk][frag]
    if (!sk0) { build_a(n0, 0, At, u0, u1, a[0][0]); build_a(n1, 0, At, u0, u1, a[1][0]); }
    if (!sk1) { build_a(n0, 1, At, u0, u1, a[0][1]); build_a(n1, 1, At, u0, u1, a[1][1]); }

#pragma unroll
    for (int sl = 0; sl < 2; ++sl) {
        const uint4* bup = (const uint4*)(sl ? bu1 : bu0);
        const uint4* blp = bup + ZROW;
#pragma unroll
        for (int m4 = 0; m4 < 4; ++m4) {
            uint4 BU = bup[m4], BL = blp[m4];
            const u32* b0p = (const u32*)&BU;
            const u32* b1p = (const u32*)&BL;
#pragma unroll
            for (int jj = 0; jj < 4; ++jj) {
                int j = m4 * 4 + jj;
                if (!sk0) mma16816(c[0][j], a[sl][0][0], a[sl][0][1], a[sl][0][2],
                                   a[sl][0][3], b0p[jj], b1p[jj]);
                if (!sk1) mma16816(c[1][j], a[sl][1][0], a[sl][1][1], a[sl][1][2],
                                   a[sl][1][3], b0p[jj], b1p[jj]);
            }
        }
    }
}

// ---------------- kernel 2: main -------------------------------------------
__global__ void __launch_bounds__(NTHREADS, 2)
setconv_h(const float* __restrict__ xt_all,
          const float* __restrict__ lsp,
          float* __restrict__ out_all)
{
    __shared__ __align__(16) u32 smem[2 * TILE_U32];

    const int cta  = blockIdx.x;        // 256 CTAs
    const int b    = cta >> 6;
    const int t0   = (cta & 63) * MT;   // sorted-t block
    const int tid  = threadIdx.x;
    const int w    = tid >> 5;
    const int lane = tid & 31;
    const int mh   = w >> 1;            // m-tile half
    const int gs   = w & 1;             // g-split half
    const int q    = lane >> 2;
    const int r    = lane & 3;

    const u32 sbase = smem_u32(smem);
    const char* gtiles = (const char*)(g_Zh + (size_t)b * NCHUNK * TILE_U32);

    float cck[2][2];
    softplus_cc(lsp, 0, cck[0][0], cck[0][1]);
    softplus_cc(lsp, 1, cck[1][0], cck[1][1]);

    // stage sorted t positions + original indices
    float2* xts = (float2*)smem;            // u32[0..63]
    u32*    xti = (u32*)smem + 64;          // u32[64..95]
    if (tid < MT) {
        u32 p = g_perm_t[b][t0 + tid];
        xti[tid] = p;
        xts[tid] = ((const float2*)xt_all)[(size_t)b * NT + p];
    }
    __syncthreads();

    float tmnx = 1e30f, tmxx = -1e30f, tmny = 1e30f, tmxy = -1e30f;
#pragma unroll
    for (int i = 0; i < MT; ++i) {
        float2 v = xts[i];
        tmnx = fminf(tmnx, v.x); tmxx = fmaxf(tmxx, v.x);
        tmny = fminf(tmny, v.y); tmxy = fmaxf(tmxy, v.y);
    }
    const int rowA = mh * 16 + q, rowB = rowA + 8;
    const float2 xvA = xts[rowA], xvB = xts[rowB];
    const u32 pA = xti[rowA], pB = xti[rowB];
    __syncthreads();    // staging region about to be overwritten by cp.async

    float At[2][2], u0[2][2], u1[2][2];   // [row A/B][kk]
#pragma unroll
    for (int kk = 0; kk < 2; ++kk) {
        At[0][kk] = fmaf(xvA.x * xvA.x, cck[kk][0], xvA.y * xvA.y * cck[kk][1]);
        u0[0][kk] = -2.f * cck[kk][0] * xvA.x;
        u1[0][kk] = -2.f * cck[kk][1] * xvA.y;
        At[1][kk] = fmaf(xvB.x * xvB.x, cck[kk][0], xvB.y * xvB.y * cck[kk][1]);
        u0[1][kk] = -2.f * cck[kk][0] * xvB.x;
        u1[1][kk] = -2.f * cck[kk][1] * xvB.y;
    }

    const u32* zb_bu0 = smem + (gs * 8 + r) * ZROW + q * 16;
    const u32* zb_bu1 = zb_bu0 + 16 * ZROW;
    const float4* zb_gm0 = (const float4*)(smem + 32 * ZROW) + gs * 16 + 2 * r;
    const float4* zb_gm1 = zb_gm0 + 32;
    const float4* zb_bb  = (const float4*)(smem + 32 * ZROW + 256);

    float c[2][16][4];                    // [kk][j][frag]
#pragma unroll
    for (int kk = 0; kk < 2; ++kk)
#pragma unroll
        for (int j = 0; j < 16; ++j) {
            c[kk][j][0] = 0.f; c[kk][j][1] = 0.f; c[kk][j][2] = 0.f; c[kk][j][3] = 0.f;
        }

    const char* gsrc = gtiles + (size_t)tid * 16;

#pragma unroll
    for (int i = 0; i < 9; ++i)
        asm volatile("cp.async.cg.shared.global [%0], [%1], 16;"
                     :: "r"(sbase + tid * 16 + i * 2048), "l"(gsrc + i * 2048) : "memory");
    asm volatile("cp.async.commit_group;" ::: "memory");
    gsrc += TILE_BYTES;

#pragma unroll 1
    for (int gc = 0; gc < NCHUNK; gc += 2) {
#pragma unroll
        for (int st = 0; st < 2; ++st) {
            asm volatile("cp.async.wait_group 0;" ::: "memory");
            __syncthreads();
            if (gc + 1 + st < NCHUNK) {
                const u32 dstb = sbase + (1 - st) * TILE_BYTES + tid * 16;
#pragma unroll
                for (int i = 0; i < 9; ++i)
                    asm volatile("cp.async.cg.shared.global [%0], [%1], 16;"
                                 :: "r"(dstb + i * 2048), "l"(gsrc + i * 2048) : "memory");
                asm volatile("cp.async.commit_group;" ::: "memory");
            }
            gsrc += TILE_BYTES;

            // per-chunk skip test (uniform across CTA)
            float4 bb = zb_bb[st * (TILE_U32 / 4)];
            float dxg = fmaxf(0.f, fmaxf(bb.x - tmxx, tmnx - bb.y));
            float dyg = fmaxf(0.f, fmaxf(bb.z - tmxy, tmny - bb.w));
            float d0 = dxg * dxg, d1 = dyg * dyg;
            bool sk0 = fmaf(d0, cck[0][0], d1 * cck[0][1]) < SKIP_THR;
            bool sk1 = fmaf(d0, cck[1][0], d1 * cck[1][1]) < SKIP_THR;

            do_chunk(zb_bu0 + st * TILE_U32, zb_bu1 + st * TILE_U32,
                     zb_gm0 + st * (TILE_U32 / 4), zb_gm1 + st * (TILE_U32 / 4),
                     sk0, sk1, At, u0, u1, c);
        }
    }

    // ---- reduce g-split pairs via smem, then scatter-store ----
    __syncthreads();
    float4* red = (float4*)smem;          // 32KB <= 36864
    if (gs == 1) {
#pragma unroll
        for (int kk = 0; kk < 2; ++kk)
#pragma unroll
            for (int j = 0; j < 16; ++j)
                red[((mh * 2 + kk) * 16 + j) * 32 + lane] =
                    make_float4(c[kk][j][0], c[kk][j][1], c[kk][j][2], c[kk][j][3]);
    }
    __syncthreads();
    if (gs == 0) {
        float* oA = out_all + ((size_t)b * NT + pA) * (DZ * 2);
        float* oB = out_all + ((size_t)b * NT + pB) * (DZ * 2);
#pragma unroll
        for (int j = 0; j < 16; ++j) {
            float4 v0 = red[((mh * 2 + 0) * 16 + j) * 32 + lane];
            float4 v1 = red[((mh * 2 + 1) * 16 + j) * 32 + lane];
            int n0 = 16 * j + 4 * r;
            *(float4*)(oA + n0) = make_float4(c[0][j][0] + v0.x, c[1][j][0] + v1.x,
                                              c[0][j][1] + v0.y, c[1][j][1] + v1.y);
            *(float4*)(oB + n0) = make_float4(c[0][j][2] + v0.z, c[1][j][2] + v1.z,
                                              c[0][j][3] + v0.w, c[1][j][3] + v1.w);
        }
    }
}

extern "C" void kernel_launch(void* const* d_in, const int* in_sizes, int n_in,
                              void* d_out, int out_size)
{
    const float* xg  = (const float*)d_in[0];   // (4,64,64,2)
    const float* zg  = (const float*)d_in[1];   // (4,64,64,128)
    const float* xt  = (const float*)d_in[2];   // (4,2048,2)
    const float* lsp = (const float*)d_in[3];   // (2,2)
    float* out = (float*)d_out;                 // (4,2048,256)

    sort_pts<<<NB * 2, 512>>>(xt, xg);
    prep_tiles<<<NB * NCHUNK, PTHREADS>>>(zg, xg, lsp);
    setconv_h<<<NB * (NT / MT), NTHREADS>>>(xt, lsp, out);
}

// round 12
// speedup vs baseline: 1.0733x; 1.0733x over previous
#include <cuda_runtime.h>
#include <cuda_fp16.h>
#include <cstdint>

// Shapes (fixed)
#define NB 4
#define NG 4096
#define DZ 128
#define NT 2048

// Tiling
#define MT 32              // t rows per CTA
#define GC 64              // g per chunk
#define NCHUNK (NG/GC)     // 64
#define ZROW 132           // u32 stride per g-pair row
#define TILE_U32 4608      // 32*ZROW(4224) + gmeta 256 + bbox/pad 128
#define TILE_BYTES (TILE_U32*4)     // 18432 = 128thr*9*16B
#define NTHREADS 128       // 4 warps: 2 mh x 2 gs (both kk per warp)
#define PTHREADS 256
#define RTHREADS 512
#define SKIP_THR (-20.0f)  // exp2 arg threshold: w < 1e-6 -> negligible

typedef unsigned int u32;

__device__ __align__(16) u32 g_Zh[(size_t)NB * NCHUNK * TILE_U32];
__device__ u32 g_perm_t[NB][NT];
__device__ u32 g_perm_g[NB][NG];

__device__ __forceinline__ float ex2f(float x) {
    float y; asm("ex2.approx.f32 %0, %1;" : "=f"(y) : "f"(x)); return y;
}
__device__ __forceinline__ u32 f16x2(float lo, float hi) {
    u32 d; asm("cvt.rn.f16x2.f32 %0, %1, %2;" : "=r"(d) : "f"(hi), "f"(lo)); return d;
}
__device__ __forceinline__ u32 smem_u32(const void* p) {
    u32 a;
    asm("{ .reg .u64 t; cvta.to.shared.u64 t, %1; cvt.u32.u64 %0, t; }" : "=r"(a) : "l"(p));
    return a;
}
__device__ __forceinline__ void mma16816(float* c, u32 a0, u32 a1, u32 a2, u32 a3,
                                         u32 b0, u32 b1) {
    asm("mma.sync.aligned.m16n8k16.row.col.f32.f16.f16.f32 "
        "{%0,%1,%2,%3}, {%4,%5,%6,%7}, {%8,%9}, {%0,%1,%2,%3};"
        : "+f"(c[0]), "+f"(c[1]), "+f"(c[2]), "+f"(c[3])
        : "r"(a0), "r"(a1), "r"(a2), "r"(a3), "r"(b0), "r"(b1));
}
__device__ __forceinline__ u32 part1by1(u32 x) {
    x &= 0xFFFF;
    x = (x | (x << 8)) & 0x00FF00FF;
    x = (x | (x << 4)) & 0x0F0F0F0F;
    x = (x | (x << 2)) & 0x33333333;
    x = (x | (x << 1)) & 0x55555555;
    return x;
}
__device__ __forceinline__ void softplus_cc(const float* lsp, int kk, float& c0, float& c1) {
    const float HL2E = 0.7213475204444817f;
    float p0 = lsp[0 * 2 + kk], p1 = lsp[1 * 2 + kk];
    float sp0 = (p0 > 20.f) ? p0 : log1pf(expf(p0));
    float sp1 = (p1 > 20.f) ? p1 : log1pf(expf(p1));
    float i0 = 1.f / (1e-5f + sp0), i1 = 1.f / (1e-5f + sp1);
    c0 = -HL2E * i0 * i0;
    c1 = -HL2E * i1 * i1;
}

// ------- kernel 0: Morton order via brute-force ranking (deterministic) ------
// Unique key = morton<<12 | idx. rank(i) = #{keys < key_i}. perm[rank] = idx.
__global__ void __launch_bounds__(RTHREADS)
rank_pts(const float* __restrict__ xt_all, const float* __restrict__ xg_all)
{
    __shared__ __align__(16) u32 keys[NG];
    const int blk = blockIdx.x;          // NB*12: per b, 4 t-segments + 8 g-segments
    const int b   = blk / 12;
    const int seg = blk % 12;
    const bool isG = seg >= 4;
    const int n   = isG ? NG : NT;
    const int base = (isG ? seg - 4 : seg) * RTHREADS;
    const float2* src = (const float2*)(isG ? xg_all : xt_all) + (size_t)b * n;
    const int tid = threadIdx.x;

    for (int i = tid; i < n; i += RTHREADS) {
        float2 v = src[i];
        int mx = min(31, max(0, (int)(v.x * 32.f)));
        int my = min(31, max(0, (int)(v.y * 32.f)));
        u32 mc = (part1by1((u32)mx) | (part1by1((u32)my) << 1)) & 0x3FF;
        keys[i] = (mc << 12) | (u32)i;
    }
    __syncthreads();

    const u32 myk = keys[base + tid];
    int rank = 0;
    const uint4* k4 = (const uint4*)keys;
#pragma unroll 8
    for (int j = 0; j < n / 4; ++j) {
        uint4 kv = k4[j];
        rank += (kv.x < myk) + (kv.y < myk) + (kv.z < myk) + (kv.w < myk);
    }
    u32* dst = isG ? g_perm_g[b] : g_perm_t[b];
    dst[rank] = myk & 0xFFF;
}

// ---------------- kernel 1: pack sorted tiles + gmeta + per-slice bbox -------
__global__ void __launch_bounds__(PTHREADS)
prep_tiles(const float* __restrict__ zg_all, const float* __restrict__ xg_all,
           const float* __restrict__ lsp)
{
    __shared__ float sx[GC], sy[GC];
    const int bc  = blockIdx.x;
    const int b   = bc >> 6;
    const int gc  = bc & 63;
    const int tid = threadIdx.x;
    const int w   = tid >> 5;
    const int z4  = tid & 31;

    u32* tile = g_Zh + (size_t)bc * TILE_U32;
    const u32* pg = g_perm_g[b] + gc * GC;

#pragma unroll
    for (int it = 0; it < 4; ++it) {
        int gp = w + it * 8;
        u32 r0 = pg[2 * gp], r1 = pg[2 * gp + 1];
        float4 v0 = __ldg((const float4*)(zg_all + ((size_t)b * NG + r0) * DZ) + z4);
        float4 v1 = __ldg((const float4*)(zg_all + ((size_t)b * NG + r1) * DZ) + z4);
        u32* dst = tile + gp * ZROW;
        int p0 = (z4 & 1) * 64 + (z4 >> 1);
        dst[p0]      = f16x2(v0.x, v1.x);
        dst[p0 + 16] = f16x2(v0.y, v1.y);
        dst[p0 + 32] = f16x2(v0.z, v1.z);
        dst[p0 + 48] = f16x2(v0.w, v1.w);
    }

    if (tid < GC) {
        float c00, c01, c10, c11;
        softplus_cc(lsp, 0, c00, c01);
        softplus_cc(lsp, 1, c10, c11);
        u32 pgi = pg[tid];
        float2 xgv = __ldg((const float2*)xg_all + (size_t)b * NG + pgi);
        float s0 = xgv.x * xgv.x, s1 = xgv.y * xgv.y;
        float Bg0 = fmaf(s0, c00, s1 * c01);
        float Bg1 = fmaf(s0, c10, s1 * c11);
        ((float4*)(tile + 32 * ZROW))[tid] = make_float4(xgv.x, xgv.y, Bg0, Bg1);
        sx[tid] = xgv.x; sy[tid] = xgv.y;
    }
    __syncthreads();
    if (tid < 2) {   // per-slice bbox: slice tid covers g [tid*32, tid*32+32)
        float mnx = 1e30f, mxx = -1e30f, mny = 1e30f, mxy = -1e30f;
        for (int i = tid * 32; i < tid * 32 + 32; ++i) {
            mnx = fminf(mnx, sx[i]); mxx = fmaxf(mxx, sx[i]);
            mny = fminf(mny, sy[i]); mxy = fmaxf(mxy, sy[i]);
        }
        ((float4*)(tile + 32 * ZROW + 256))[tid] = make_float4(mnx, mxx, mny, mxy);
    }
}

// -------- A-fragment builder: one slice, one kk --------
__device__ __forceinline__ void build_a(
    const float4* m, int kk,
    const float (&At)[2][2], const float (&u0)[2][2], const float (&u1)[2][2],
    u32 (&a)[4])
{
    float wvA[4], wvB[4];
#pragma unroll
    for (int i = 0; i < 4; ++i) {
        float Bv = kk ? m[i].w : m[i].z;
        wvA[i] = ex2f(fmaf(m[i].x, u0[0][kk], fmaf(m[i].y, u1[0][kk], Bv)) + At[0][kk]);
        wvB[i] = ex2f(fmaf(m[i].x, u0[1][kk], fmaf(m[i].y, u1[1][kk], Bv)) + At[1][kk]);
    }
    a[0] = f16x2(wvA[0], wvA[1]);
    a[1] = f16x2(wvB[0], wvB[1]);
    a[2] = f16x2(wvA[2], wvA[3]);
    a[3] = f16x2(wvB[2], wvB[3]);
}

// -------- one 32-g slice: B loads + unconditional k1, branch-wrapped k0 ------
__device__ __forceinline__ void do_half(
    const u32* bu, const float4* gm, bool sk0, bool sk1,
    const float (&At)[2][2], const float (&u0)[2][2], const float (&u1)[2][2],
    float (&c)[2][16][4])
{
    const uint4* bup = (const uint4*)bu;
    const uint4* blp = bup + ZROW;
    uint4 BU[4], BL[4];
#pragma unroll
    for (int m = 0; m < 4; ++m) { BU[m] = bup[m]; BL[m] = blp[m]; }
    float4 n[4] = { gm[0], gm[1], gm[8], gm[9] };

    if (!sk1) {
        u32 a[4];
        build_a(n, 1, At, u0, u1, a);
#pragma unroll
        for (int j = 0; j < 16; ++j)
            mma16816(c[1][j], a[0], a[1], a[2], a[3],
                     ((const u32*)BU)[j], ((const u32*)BL)[j]);
    }
    if (!sk0) {
        u32 a[4];
        build_a(n, 0, At, u0, u1, a);
#pragma unroll
        for (int j = 0; j < 16; ++j)
            mma16816(c[0][j], a[0], a[1], a[2], a[3],
                     ((const u32*)BU)[j], ((const u32*)BL)[j]);
    }
}

// ---------------- kernel 2: main -------------------------------------------
__global__ void __launch_bounds__(NTHREADS, 2)
setconv_h(const float* __restrict__ xt_all,
          const float* __restrict__ lsp,
          float* __restrict__ out_all)
{
    __shared__ __align__(16) u32 smem[2 * TILE_U32];

    const int cta  = blockIdx.x;        // 256 CTAs
    const int b    = cta >> 6;
    const int t0   = (cta & 63) * MT;   // sorted-t block
    const int tid  = threadIdx.x;
    const int w    = tid >> 5;
    const int lane = tid & 31;
    const int mh   = w >> 1;            // m-tile half
    const int gs   = w & 1;             // g-split half
    const int q    = lane >> 2;
    const int r    = lane & 3;

    const u32 sbase = smem_u32(smem);
    const char* gtiles = (const char*)(g_Zh + (size_t)b * NCHUNK * TILE_U32);

    float cck[2][2];
    softplus_cc(lsp, 0, cck[0][0], cck[0][1]);
    softplus_cc(lsp, 1, cck[1][0], cck[1][1]);

    // stage sorted t positions + original indices
    float2* xts = (float2*)smem;
    u32*    xti = (u32*)smem + 64;
    if (tid < MT) {
        u32 p = g_perm_t[b][t0 + tid];
        xti[tid] = p;
        xts[tid] = ((const float2*)xt_all)[(size_t)b * NT + p];
    }
    __syncthreads();

    float tmnx = 1e30f, tmxx = -1e30f, tmny = 1e30f, tmxy = -1e30f;
#pragma unroll
    for (int i = 0; i < MT; ++i) {
        float2 v = xts[i];
        tmnx = fminf(tmnx, v.x); tmxx = fmaxf(tmxx, v.x);
        tmny = fminf(tmny, v.y); tmxy = fmaxf(tmxy, v.y);
    }
    const int rowA = mh * 16 + q, rowB = rowA + 8;
    const float2 xvA = xts[rowA], xvB = xts[rowB];
    const u32 pA = xti[rowA], pB = xti[rowB];
    __syncthreads();

    float At[2][2], u0[2][2], u1[2][2];   // [row A/B][kk]
#pragma unroll
    for (int kk = 0; kk < 2; ++kk) {
        At[0][kk] = fmaf(xvA.x * xvA.x, cck[kk][0], xvA.y * xvA.y * cck[kk][1]);
        u0[0][kk] = -2.f * cck[kk][0] * xvA.x;
        u1[0][kk] = -2.f * cck[kk][1] * xvA.y;
        At[1][kk] = fmaf(xvB.x * xvB.x, cck[kk][0], xvB.y * xvB.y * cck[kk][1]);
        u0[1][kk] = -2.f * cck[kk][0] * xvB.x;
        u1[1][kk] = -2.f * cck[kk][1] * xvB.y;
    }

    const u32* zb_bu0 = smem + (gs * 8 + r) * ZROW + q * 16;   // slice gs
    const u32* zb_bu1 = zb_bu0 + 16 * ZROW;                    // slice gs+2
    const float4* zb_gm0 = (const float4*)(smem + 32 * ZROW) + gs * 16 + 2 * r;
    const float4* zb_gm1 = zb_gm0 + 32;
    const float4* zb_bb  = (const float4*)(smem + 32 * ZROW + 256);

    float c[2][16][4];
#pragma unroll
    for (int kk = 0; kk < 2; ++kk)
#pragma unroll
        for (int j = 0; j < 16; ++j) {
            c[kk][j][0] = 0.f; c[kk][j][1] = 0.f; c[kk][j][2] = 0.f; c[kk][j][3] = 0.f;
        }

    const char* gsrc = gtiles + (size_t)tid * 16;

#pragma unroll
    for (int i = 0; i < 9; ++i)
        asm volatile("cp.async.cg.shared.global [%0], [%1], 16;"
                     :: "r"(sbase + tid * 16 + i * 2048), "l"(gsrc + i * 2048) : "memory");
    asm volatile("cp.async.commit_group;" ::: "memory");
    gsrc += TILE_BYTES;

#pragma unroll 1
    for (int gc = 0; gc < NCHUNK; gc += 2) {
#pragma unroll
        for (int st = 0; st < 2; ++st) {
            asm volatile("cp.async.wait_group 0;" ::: "memory");
            __syncthreads();
            if (gc + 1 + st < NCHUNK) {
                const u32 dstb = sbase + (1 - st) * TILE_BYTES + tid * 16;
#pragma unroll
                for (int i = 0; i < 9; ++i)
                    asm volatile("cp.async.cg.shared.global [%0], [%1], 16;"
                                 :: "r"(dstb + i * 2048), "l"(gsrc + i * 2048) : "memory");
                asm volatile("cp.async.commit_group;" ::: "memory");
            }
            gsrc += TILE_BYTES;

            // per-slice skip test (uniform across CTA): warp's slices = gs, gs+2
            const float4* bb = zb_bb + st * (TILE_U32 / 4);
            bool sk0[2], sk1[2];
#pragma unroll
            for (int sl = 0; sl < 2; ++sl) {
                float4 bx = bb[sl];   // slice index within chunk: this warp's two
                // NOTE: slices within chunk are [0..31]=bbox0, [32..63]=bbox1;
                // warp handles slice gs (rows gs*8..) and gs+2 -> both within
                // halves: rows (gs*8+r) covers g-pairs gs*8..gs*8+7 => g 16gs..16gs+15
                // and +16*ZROW => g 16gs+32.. ; map: half0 = g<32 (bbox[0]), half1 = bbox[1]
                (void)bx;
                sk0[sl] = false; sk1[sl] = false;
            }
            {
                // slice A (g 16gs..16gs+15): inside bbox half (16gs)/32
                float4 b0 = bb[(16 * gs) >> 5];
                float dx = fmaxf(0.f, fmaxf(b0.x - tmxx, tmnx - b0.y));
                float dy = fmaxf(0.f, fmaxf(b0.z - tmxy, tmny - b0.w));
                float d0 = dx * dx, d1 = dy * dy;
                sk0[0] = fmaf(d0, cck[0][0], d1 * cck[0][1]) < SKIP_THR;
                sk1[0] = fmaf(d0, cck[1][0], d1 * cck[1][1]) < SKIP_THR;
                float4 b1 = bb[(16 * gs + 32) >> 5];
                dx = fmaxf(0.f, fmaxf(b1.x - tmxx, tmnx - b1.y));
                dy = fmaxf(0.f, fmaxf(b1.z - tmxy, tmny - b1.w));
                d0 = dx * dx; d1 = dy * dy;
                sk0[1] = fmaf(d0, cck[0][0], d1 * cck[0][1]) < SKIP_THR;
                sk1[1] = fmaf(d0, cck[1][0], d1 * cck[1][1]) < SKIP_THR;
            }

            do_half(zb_bu0 + st * TILE_U32, zb_gm0 + st * (TILE_U32 / 4),
                    sk0[0], sk1[0], At, u0, u1, c);
            do_half(zb_bu1 + st * TILE_U32, zb_gm1 + st * (TILE_U32 / 4),
                    sk0[1], sk1[1], At, u0, u1, c);
        }
    }

    // ---- reduce g-split pairs via smem, then scatter-store ----
    __syncthreads();
    float4* red = (float4*)smem;
    if (gs == 1) {
#pragma unroll
        for (int kk = 0; kk < 2; ++kk)
#pragma unroll
            for (int j = 0; j < 16; ++j)
                red[((mh * 2 + kk) * 16 + j) * 32 + lane] =
                    make_float4(c[kk][j][0], c[kk][j][1], c[kk][j][2], c[kk][j][3]);
    }
    __syncthreads();
    if (gs == 0) {
        float* oA = out_all + ((size_t)b * NT + pA) * (DZ * 2);
        float* oB = out_all + ((size_t)b * NT + pB) * (DZ * 2);
#pragma unroll
        for (int j = 0; j < 16; ++j) {
            float4 v0 = red[((mh * 2 + 0) * 16 + j) * 32 + lane];
            float4 v1 = red[((mh * 2 + 1) * 16 + j) * 32 + lane];
            int n0 = 16 * j + 4 * r;
            *(float4*)(oA + n0) = make_float4(c[0][j][0] + v0.x, c[1][j][0] + v1.x,
                                              c[0][j][1] + v0.y, c[1][j][1] + v1.y);
            *(float4*)(oB + n0) = make_float4(c[0][j][2] + v0.z, c[1][j][2] + v1.z,
                                              c[0][j][3] + v0.w, c[1][j][3] + v1.w);
        }
    }
}

extern "C" void kernel_launch(void* const* d_in, const int* in_sizes, int n_in,
                              void* d_out, int out_size)
{
    const float* xg  = (const float*)d_in[0];   // (4,64,64,2)
    const float* zg  = (const float*)d_in[1];   // (4,64,64,128)
    const float* xt  = (const float*)d_in[2];   // (4,2048,2)
    const float* lsp = (const float*)d_in[3];   // (2,2)
    float* out = (float*)d_out;                 // (4,2048,256)

    rank_pts<<<NB * 12, RTHREADS>>>(xt, xg);
    prep_tiles<<<NB * NCHUNK, PTHREADS>>>(zg, xg, lsp);
    setconv_h<<<NB * (NT / MT), NTHREADS>>>(xt, lsp, out);
}

// round 13
// speedup vs baseline: 1.2812x; 1.1936x over previous
#include <cuda_runtime.h>
#include <cuda_fp16.h>
#include <cstdint>

// Shapes (fixed)
#define NB 4
#define NG 4096
#define DZ 128
#define NT 2048

// Tiling
#define MT 32              // t rows per CTA
#define GC 64              // g per chunk
#define NCHUNK (NG/GC)     // 64
#define ZROW 132           // u32 stride per g-pair row
#define TILE_U32 4608      // 32*ZROW(4224) + gmeta 256 + bbox 64 + pad
#define TILE_BYTES (TILE_U32*4)     // 18432 = 128thr*9*16B
#define NTHREADS 128       // 4 warps: 2 mh x 2 gs (both kk per warp)
#define PTHREADS 256
#define RT 512
#define SKIP_THR (-16.0f)  // exp2 arg threshold: w < 1.6e-5 -> negligible

typedef unsigned int u32;

__device__ __align__(16) u32 g_Zh[(size_t)NB * NCHUNK * TILE_U32];
__device__ int g_rank[NB][2][4096];      // [arr: 0=t,1=g]; zeroed per launch
__device__ u32 g_perm_t[NB][NT];
__device__ u32 g_perm_g[NB][NG];

__device__ __forceinline__ float ex2f(float x) {
    float y; asm("ex2.approx.f32 %0, %1;" : "=f"(y) : "f"(x)); return y;
}
__device__ __forceinline__ u32 f16x2(float lo, float hi) {
    u32 d; asm("cvt.rn.f16x2.f32 %0, %1, %2;" : "=r"(d) : "f"(hi), "f"(lo)); return d;
}
__device__ __forceinline__ u32 smem_u32(const void* p) {
    u32 a;
    asm("{ .reg .u64 t; cvta.to.shared.u64 t, %1; cvt.u32.u64 %0, t; }" : "=r"(a) : "l"(p));
    return a;
}
__device__ __forceinline__ void mma16816(float* c, u32 a0, u32 a1, u32 a2, u32 a3,
                                         u32 b0, u32 b1) {
    asm("mma.sync.aligned.m16n8k16.row.col.f32.f16.f16.f32 "
        "{%0,%1,%2,%3}, {%4,%5,%6,%7}, {%8,%9}, {%0,%1,%2,%3};"
        : "+f"(c[0]), "+f"(c[1]), "+f"(c[2]), "+f"(c[3])
        : "r"(a0), "r"(a1), "r"(a2), "r"(a3), "r"(b0), "r"(b1));
}
__device__ __forceinline__ u32 part1by1(u32 x) {
    x &= 0xFFFF;
    x = (x | (x << 8)) & 0x00FF00FF;
    x = (x | (x << 4)) & 0x0F0F0F0F;
    x = (x | (x << 2)) & 0x33333333;
    x = (x | (x << 1)) & 0x55555555;
    return x;
}
__device__ __forceinline__ u32 mcode(float2 v) {
    int mx = min(31, max(0, (int)(v.x * 32.f)));
    int my = min(31, max(0, (int)(v.y * 32.f)));
    return (part1by1((u32)mx) | (part1by1((u32)my) << 1)) & 0x3FF;
}
__device__ __forceinline__ void softplus_cc(const float* lsp, int kk, float& c0, float& c1) {
    const float HL2E = 0.7213475204444817f;
    float p0 = lsp[0 * 2 + kk], p1 = lsp[1 * 2 + kk];
    float sp0 = (p0 > 20.f) ? p0 : log1pf(expf(p0));
    float sp1 = (p1 > 20.f) ? p1 : log1pf(expf(p1));
    float i0 = 1.f / (1e-5f + sp0), i1 = 1.f / (1e-5f + sp1);
    c0 = -HL2E * i0 * i0;
    c1 = -HL2E * i1 * i1;
}

// ------- kernel 0: partial ranks (deterministic int atomics) ------------------
// Per b: 16 (t: 4 seg x 4 part) + 64 (g: 8 seg x 8 part) blocks of 512.
__global__ void __launch_bounds__(RT)
rank_pts(const float* __restrict__ xt_all, const float* __restrict__ xg_all)
{
    __shared__ __align__(16) u32 keys[RT];
    const int blk = blockIdx.x;
    const int b   = blk / 80;
    const int q   = blk % 80;
    const bool isG = q >= 16;
    int si, pj;
    const float2* src;
    if (isG) { int qq = q - 16; si = qq >> 3; pj = qq & 7;
               src = (const float2*)xg_all + (size_t)b * NG; }
    else     { si = q >> 2; pj = q & 3;
               src = (const float2*)xt_all + (size_t)b * NT; }
    const int tid = threadIdx.x;

    const int myi = si * RT + tid;
    const u32 myk = (mcode(src[myi]) << 12) | (u32)myi;
    const int pi  = pj * RT + tid;
    keys[tid] = (mcode(src[pi]) << 12) | (u32)pi;
    __syncthreads();

    int cnt = 0;
    const uint4* k4 = (const uint4*)keys;
#pragma unroll 16
    for (int j = 0; j < RT / 4; ++j) {
        uint4 kv = k4[j];
        cnt += (kv.x < myk) + (kv.y < myk) + (kv.z < myk) + (kv.w < myk);
    }
    atomicAdd(&g_rank[b][isG ? 1 : 0][myi], cnt);
}

// ------- kernel 0b: invert rank -> permutation --------------------------------
__global__ void __launch_bounds__(RT)
scatter_perm()
{
    const int i = blockIdx.x * RT + threadIdx.x;    // 0..NB*6144-1
    const int b = i / 6144;
    const int s = i % 6144;
    if (s < NT) g_perm_t[b][g_rank[b][0][s]] = (u32)s;
    else {
        int gi = s - NT;
        g_perm_g[b][g_rank[b][1][gi]] = (u32)gi;
    }
}

// ---------------- kernel 1: pack sorted tiles + gmeta + per-16g bbox ----------
__global__ void __launch_bounds__(PTHREADS)
prep_tiles(const float* __restrict__ zg_all, const float* __restrict__ xg_all,
           const float* __restrict__ lsp)
{
    __shared__ float sx[GC], sy[GC];
    const int bc  = blockIdx.x;
    const int b   = bc >> 6;
    const int gc  = bc & 63;
    const int tid = threadIdx.x;
    const int w   = tid >> 5;
    const int z4  = tid & 31;

    u32* tile = g_Zh + (size_t)bc * TILE_U32;
    const u32* pg = g_perm_g[b] + gc * GC;

#pragma unroll
    for (int it = 0; it < 4; ++it) {
        int gp = w + it * 8;
        u32 r0 = pg[2 * gp], r1 = pg[2 * gp + 1];
        float4 v0 = __ldg((const float4*)(zg_all + ((size_t)b * NG + r0) * DZ) + z4);
        float4 v1 = __ldg((const float4*)(zg_all + ((size_t)b * NG + r1) * DZ) + z4);
        u32* dst = tile + gp * ZROW;
        int p0 = (z4 & 1) * 64 + (z4 >> 1);
        dst[p0]      = f16x2(v0.x, v1.x);
        dst[p0 + 16] = f16x2(v0.y, v1.y);
        dst[p0 + 32] = f16x2(v0.z, v1.z);
        dst[p0 + 48] = f16x2(v0.w, v1.w);
    }

    if (tid < GC) {
        float c00, c01, c10, c11;
        softplus_cc(lsp, 0, c00, c01);
        softplus_cc(lsp, 1, c10, c11);
        u32 pgi = pg[tid];
        float2 xgv = __ldg((const float2*)xg_all + (size_t)b * NG + pgi);
        float s0 = xgv.x * xgv.x, s1 = xgv.y * xgv.y;
        float Bg0 = fmaf(s0, c00, s1 * c01);
        float Bg1 = fmaf(s0, c10, s1 * c11);
        ((float4*)(tile + 32 * ZROW))[tid] = make_float4(xgv.x, xgv.y, Bg0, Bg1);
        sx[tid] = xgv.x; sy[tid] = xgv.y;
    }
    __syncthreads();
    if (tid < 4) {   // bbox per 16-g slice
        float mnx = 1e30f, mxx = -1e30f, mny = 1e30f, mxy = -1e30f;
        for (int i = tid * 16; i < tid * 16 + 16; ++i) {
            mnx = fminf(mnx, sx[i]); mxx = fmaxf(mxx, sx[i]);
            mny = fminf(mny, sy[i]); mxy = fmaxf(mxy, sy[i]);
        }
        ((float4*)(tile + 32 * ZROW + 256))[tid] = make_float4(mnx, mxx, mny, mxy);
    }
}

// -------- A-fragment builder: one 16-g slice, one kk --------
__device__ __forceinline__ void build_a(
    const float4* m, int kk,
    const float (&At)[2][2], const float (&u0)[2][2], const float (&u1)[2][2],
    u32 (&a)[4])
{
    float wvA[4], wvB[4];
#pragma unroll
    for (int i = 0; i < 4; ++i) {
        float Bv = kk ? m[i].w : m[i].z;
        wvA[i] = ex2f(fmaf(m[i].x, u0[0][kk], fmaf(m[i].y, u1[0][kk], Bv)) + At[0][kk]);
        wvB[i] = ex2f(fmaf(m[i].x, u0[1][kk], fmaf(m[i].y, u1[1][kk], Bv)) + At[1][kk]);
    }
    a[0] = f16x2(wvA[0], wvA[1]);
    a[1] = f16x2(wvB[0], wvB[1]);
    a[2] = f16x2(wvA[2], wvA[3]);
    a[3] = f16x2(wvB[2], wvB[3]);
}

// -------- one 16-g slice --------
__device__ __forceinline__ void do_half(
    const u32* bu, const float4* gm, bool sk0, bool sk1,
    const float (&At)[2][2], const float (&u0)[2][2], const float (&u1)[2][2],
    float (&c)[2][16][4])
{
    if (sk0 && sk1) return;
    const uint4* bup = (const uint4*)bu;
    const uint4* blp = bup + ZROW;
    uint4 BU[4], BL[4];
#pragma unroll
    for (int m = 0; m < 4; ++m) { BU[m] = bup[m]; BL[m] = blp[m]; }
    float4 n[4] = { gm[0], gm[1], gm[8], gm[9] };

    if (!sk1) {
        u32 a[4];
        build_a(n, 1, At, u0, u1, a);
#pragma unroll
        for (int j = 0; j < 16; ++j)
            mma16816(c[1][j], a[0], a[1], a[2], a[3],
                     ((const u32*)BU)[j], ((const u32*)BL)[j]);
    }
    if (!sk0) {
        u32 a[4];
        build_a(n, 0, At, u0, u1, a);
#pragma unroll
        for (int j = 0; j < 16; ++j)
            mma16816(c[0][j], a[0], a[1], a[2], a[3],
                     ((const u32*)BU)[j], ((const u32*)BL)[j]);
    }
}

// ---------------- kernel 2: main -------------------------------------------
__global__ void __launch_bounds__(NTHREADS, 2)
setconv_h(const float* __restrict__ xt_all,
          const float* __restrict__ lsp,
          float* __restrict__ out_all)
{
    __shared__ __align__(16) u32 smem[2 * TILE_U32];

    const int cta  = blockIdx.x;        // 256 CTAs
    const int b    = cta >> 6;
    const int t0   = (cta & 63) * MT;   // sorted-t block
    const int tid  = threadIdx.x;
    const int w    = tid >> 5;
    const int lane = tid & 31;
    const int mh   = w >> 1;            // m-tile half
    const int gs   = w & 1;             // g-split half
    const int q    = lane >> 2;
    const int r    = lane & 3;

    const u32 sbase = smem_u32(smem);
    const char* gtiles = (const char*)(g_Zh + (size_t)b * NCHUNK * TILE_U32);

    float cck[2][2];
    softplus_cc(lsp, 0, cck[0][0], cck[0][1]);
    softplus_cc(lsp, 1, cck[1][0], cck[1][1]);

    // stage sorted t positions + original indices
    float2* xts = (float2*)smem;
    u32*    xti = (u32*)smem + 64;
    if (tid < MT) {
        u32 p = g_perm_t[b][t0 + tid];
        xti[tid] = p;
        xts[tid] = ((const float2*)xt_all)[(size_t)b * NT + p];
    }
    __syncthreads();

    // per-warp (mh) t-bbox over this warp's 16 rows
    float tmnx = 1e30f, tmxx = -1e30f, tmny = 1e30f, tmxy = -1e30f;
#pragma unroll
    for (int i = 0; i < 16; ++i) {
        float2 v = xts[mh * 16 + i];
        tmnx = fminf(tmnx, v.x); tmxx = fmaxf(tmxx, v.x);
        tmny = fminf(tmny, v.y); tmxy = fmaxf(tmxy, v.y);
    }
    const int rowA = mh * 16 + q, rowB = rowA + 8;
    const float2 xvA = xts[rowA], xvB = xts[rowB];
    const u32 pA = xti[rowA], pB = xti[rowB];
    __syncthreads();

    float At[2][2], u0[2][2], u1[2][2];
#pragma unroll
    for (int kk = 0; kk < 2; ++kk) {
        At[0][kk] = fmaf(xvA.x * xvA.x, cck[kk][0], xvA.y * xvA.y * cck[kk][1]);
        u0[0][kk] = -2.f * cck[kk][0] * xvA.x;
        u1[0][kk] = -2.f * cck[kk][1] * xvA.y;
        At[1][kk] = fmaf(xvB.x * xvB.x, cck[kk][0], xvB.y * xvB.y * cck[kk][1]);
        u0[1][kk] = -2.f * cck[kk][0] * xvB.x;
        u1[1][kk] = -2.f * cck[kk][1] * xvB.y;
    }

    const u32* zb_bu0 = smem + (gs * 8 + r) * ZROW + q * 16;   // g 16gs..16gs+15
    const u32* zb_bu1 = zb_bu0 + 16 * ZROW;                    // g 16gs+32..
    const float4* zb_gm0 = (const float4*)(smem + 32 * ZROW) + gs * 16 + 2 * r;
    const float4* zb_gm1 = zb_gm0 + 32;
    const float4* zb_bb  = (const float4*)(smem + 32 * ZROW + 256);

    float c[2][16][4];
#pragma unroll
    for (int kk = 0; kk < 2; ++kk)
#pragma unroll
        for (int j = 0; j < 16; ++j) {
            c[kk][j][0] = 0.f; c[kk][j][1] = 0.f; c[kk][j][2] = 0.f; c[kk][j][3] = 0.f;
        }

    const char* gsrc = gtiles + (size_t)tid * 16;

#pragma unroll
    for (int i = 0; i < 9; ++i)
        asm volatile("cp.async.cg.shared.global [%0], [%1], 16;"
                     :: "r"(sbase + tid * 16 + i * 2048), "l"(gsrc + i * 2048) : "memory");
    asm volatile("cp.async.commit_group;" ::: "memory");
    gsrc += TILE_BYTES;

#pragma unroll 1
    for (int gc = 0; gc < NCHUNK; gc += 2) {
#pragma unroll
        for (int st = 0; st < 2; ++st) {
            asm volatile("cp.async.wait_group 0;" ::: "memory");
            __syncthreads();
            if (gc + 1 + st < NCHUNK) {
                const u32 dstb = sbase + (1 - st) * TILE_BYTES + tid * 16;
#pragma unroll
                for (int i = 0; i < 9; ++i)
                    asm volatile("cp.async.cg.shared.global [%0], [%1], 16;"
                                 :: "r"(dstb + i * 2048), "l"(gsrc + i * 2048) : "memory");
                asm volatile("cp.async.commit_group;" ::: "memory");
            }
            gsrc += TILE_BYTES;

            // per-16g-slice skip tests (warp-uniform; this warp's slices: gs, gs+2)
            const float4* bb = zb_bb + st * (TILE_U32 / 4);
            bool sk0a, sk1a, sk0b, sk1b;
            {
                float4 b0 = bb[gs];
                float dx = fmaxf(0.f, fmaxf(b0.x - tmxx, tmnx - b0.y));
                float dy = fmaxf(0.f, fmaxf(b0.z - tmxy, tmny - b0.w));
                float d0 = dx * dx, d1 = dy * dy;
                sk0a = fmaf(d0, cck[0][0], d1 * cck[0][1]) < SKIP_THR;
                sk1a = fmaf(d0, cck[1][0], d1 * cck[1][1]) < SKIP_THR;
                float4 b1 = bb[gs + 2];
                dx = fmaxf(0.f, fmaxf(b1.x - tmxx, tmnx - b1.y));
                dy = fmaxf(0.f, fmaxf(b1.z - tmxy, tmny - b1.w));
                d0 = dx * dx; d1 = dy * dy;
                sk0b = fmaf(d0, cck[0][0], d1 * cck[0][1]) < SKIP_THR;
                sk1b = fmaf(d0, cck[1][0], d1 * cck[1][1]) < SKIP_THR;
            }

            do_half(zb_bu0 + st * TILE_U32, zb_gm0 + st * (TILE_U32 / 4),
                    sk0a, sk1a, At, u0, u1, c);
            do_half(zb_bu1 + st * TILE_U32, zb_gm1 + st * (TILE_U32 / 4),
                    sk0b, sk1b, At, u0, u1, c);
        }
    }

    // ---- reduce g-split pairs via smem, then scatter-store ----
    __syncthreads();
    float4* red = (float4*)smem;
    if (gs == 1) {
#pragma unroll
        for (int kk = 0; kk < 2; ++kk)
#pragma unroll
            for (int j = 0; j < 16; ++j)
                red[((mh * 2 + kk) * 16 + j) * 32 + lane] =
                    make_float4(c[kk][j][0], c[kk][j][1], c[kk][j][2], c[kk][j][3]);
    }
    __syncthreads();
    if (gs == 0) {
        float* oA = out_all + ((size_t)b * NT + pA) * (DZ * 2);
        float* oB = out_all + ((size_t)b * NT + pB) * (DZ * 2);
#pragma unroll
        for (int j = 0; j < 16; ++j) {
            float4 v0 = red[((mh * 2 + 0) * 16 + j) * 32 + lane];
            float4 v1 = red[((mh * 2 + 1) * 16 + j) * 32 + lane];
            int n0 = 16 * j + 4 * r;
            *(float4*)(oA + n0) = make_float4(c[0][j][0] + v0.x, c[1][j][0] + v1.x,
                                              c[0][j][1] + v0.y, c[1][j][1] + v1.y);
            *(float4*)(oB + n0) = make_float4(c[0][j][2] + v0.z, c[1][j][2] + v1.z,
                                              c[0][j][3] + v0.w, c[1][j][3] + v1.w);
        }
    }
}

extern "C" void kernel_launch(void* const* d_in, const int* in_sizes, int n_in,
                              void* d_out, int out_size)
{
    const float* xg  = (const float*)d_in[0];   // (4,64,64,2)
    const float* zg  = (const float*)d_in[1];   // (4,64,64,128)
    const float* xt  = (const float*)d_in[2];   // (4,2048,2)
    const float* lsp = (const float*)d_in[3];   // (2,2)
    float* out = (float*)d_out;                 // (4,2048,256)

    void* rank_addr = nullptr;
    cudaGetSymbolAddress(&rank_addr, g_rank);
    cudaMemsetAsync(rank_addr, 0, sizeof(int) * NB * 2 * 4096);

    rank_pts<<<NB * 80, RT>>>(xt, xg);
    scatter_perm<<<NB * 6144 / RT, RT>>>();
    prep_tiles<<<NB * NCHUNK, PTHREADS>>>(zg, xg, lsp);
    setconv_h<<<NB * (NT / MT), NTHREADS>>>(xt, lsp, out);
}